// round 7
// baseline (speedup 1.0000x reference)
#include <cuda_runtime.h>
#include <cuda_fp16.h>
#include <cstdint>

// LSTMPredictor: persistent-CTA fused 2-layer LSTM.
// R7: f16x2 packed gate activations (0.5-prescale baked into weights),
// dead n-tile skip, ldmatrix A-fragments, 2 barriers/step (3 in future phase).
// Weights + c-state in registers; double-buffered h/x operand matrix in SMEM.
//
// Grid 256 CTAs x 256 thr, BT=32 rows/CTA, 2 CTAs/SM.
// fp16 mma.m16n8k16: G[32 x 256pad] = A[32 x 64] @ W.
//   K: 0..50 h, 51 x/out, 52 bias(1.0), 53..63 zero
//   N: gate rows permuted n = 4j+q, q={i,f,g,o}; i/f/o rows pre-scaled 0.5.

#define NLAY_OFF 8192
#define WF_TOTAL 16384
#define ASTR 72
#define RSTR 9
#define BT   32
#define TPB  256
#define TSEQ 2048
#define TTOT 2112
#define NCTA 256

__device__ __align__(16) uint32_t d_Wf[WF_TOTAL];

__device__ __forceinline__ float tanh_ap(float x) {
    float y; asm("tanh.approx.f32 %0, %1;" : "=f"(y) : "f"(x)); return y;
}
__device__ __forceinline__ __half2 tanh2_ap(__half2 a) {
    uint32_t r, u = *(uint32_t*)&a;
    asm("tanh.approx.f16x2 %0, %1;" : "=r"(r) : "r"(u));
    return *(__half2*)&r;
}

#define LDSM4(d, addr)                                                        \
    asm volatile("ldmatrix.sync.aligned.m8n8.x4.shared.b16 {%0,%1,%2,%3}, [%4];" \
                 : "=r"(d[0]), "=r"(d[1]), "=r"(d[2]), "=r"(d[3]) : "r"(addr))

// ---------------------------------------------------------------------------
// Fragment-ordered fp16 weights (R4-R6 verified encoding; nt padded to 32).
// u = L*8192 + ((kt*32 + nt)*32 + lane)*2 + r
// pair = W[k0][n], W[k0+1][n]; k0 = kt*16 + r*8 + 2*(lane&3); n = nt*8 + (lane>>2)
// n -> gate row: j = n>>2, q = n&3, row = q*51 + j.  q in {i,f,g,o}:
// sigmoid gates (q != 2) pre-scaled by 0.5 (sig(x) = 0.5 + 0.5*tanh(0.5x)).
__global__ void prep_weights(const float* __restrict__ Wih1, const float* __restrict__ Whh1,
                             const float* __restrict__ bih1, const float* __restrict__ bhh1,
                             const float* __restrict__ Wih2, const float* __restrict__ Whh2,
                             const float* __restrict__ bih2, const float* __restrict__ bhh2) {
    int u = blockIdx.x * blockDim.x + threadIdx.x;
    if (u >= WF_TOTAL) return;
    int L    = u / NLAY_OFF;
    int w    = u - L * NLAY_OFF;
    int r    = w & 1;
    int lane = (w >> 1) & 31;
    int t2   = w >> 6;
    int nt   = t2 & 31;
    int kt   = t2 >> 5;
    int n    = nt * 8 + (lane >> 2);
    int k0   = kt * 16 + r * 8 + 2 * (lane & 3);
    float v[2];
#pragma unroll
    for (int i = 0; i < 2; i++) {
        int k = k0 + i;
        float val = 0.0f;
        if (n < 204) {
            int j = n >> 2, q = n & 3;
            int row = q * 51 + j;
            if (k < 51)
                val = (L == 0) ? Whh1[row * 51 + k]
                               : (Wih2[row * 51 + k] + Whh2[row * 51 + k]);
            else if (k == 51)
                val = (L == 0) ? Wih1[row] : 0.0f;
            else if (k == 52)
                val = (L == 0) ? (bih1[row] + bhh1[row]) : (bih2[row] + bhh2[row]);
            if (q != 2) val *= 0.5f;          // sigmoid pre-scale
        }
        v[i] = val;
    }
    __half2 h = __floats2half2_rn(v[0], v[1]);
    d_Wf[u] = *(uint32_t*)&h;
}

// ---------------------------------------------------------------------------
__global__ void __launch_bounds__(TPB, 2)
lstm_main(const float* __restrict__ x,
          const float* __restrict__ Wout, const float* __restrict__ bout,
          float* __restrict__ out) {
    __shared__ __half Asb[2][BT * ASTR];
    __shared__ float  Rs2[BT * RSTR];

    const int tid  = threadIdx.x;
    const int lane = tid & 31;
    const int wrp  = tid >> 5;
    const int gb0  = blockIdx.x * BT;
    const int g    = lane >> 2, tig = lane & 3;
    const int oddl = tig & 1;
    const int ntBeg = wrp * 4;
    const bool alive = (ntBeg <= 25);

    // ---- one-time init ----
    for (int i = tid; i < BT * ASTR; i += TPB) {
        __half v = __float2half_rn((i % ASTR) == 52 ? 1.0f : 0.0f);
        Asb[0][i] = v; Asb[1][i] = v;
    }
    for (int i = tid; i < BT * RSTR; i += TPB) Rs2[i] = 0.0f;
    if (tid < BT)
        Asb[0][tid * ASTR + 51] = __float2half_rn(x[(size_t)(gb0 + tid) * TSEQ]);
    float xnext = (tid < BT) ? x[(size_t)(gb0 + tid) * TSEQ + 1] : 0.0f;

    // B fragments -> registers
    uint32_t Br[2][4][4][2];
#pragma unroll
    for (int L = 0; L < 2; L++)
#pragma unroll
        for (int ni = 0; ni < 4; ni++)
#pragma unroll
            for (int kt = 0; kt < 4; kt++) {
                uint2 v = *(const uint2*)&d_Wf[L * NLAY_OFF +
                            (((kt * 32) + (ntBeg + ni)) * 32 + lane) * 2];
                Br[L][ni][kt][0] = v.x; Br[L][ni][kt][1] = v.y;
            }

    const float bo = bout[0];
    float woj[4];
#pragma unroll
    for (int ni = 0; ni < 4; ni++) {
        int j = 2 * (ntBeg + ni) + (tig >> 1);
        woj[ni] = (j < 51) ? Wout[j] : 0.0f;
    }

    float creg[2][4];
#pragma unroll
    for (int mt = 0; mt < 2; mt++)
#pragma unroll
        for (int ni = 0; ni < 4; ni++) creg[mt][ni] = 0.0f;

    // ldmatrix per-lane address offset (bytes): matrix id lm = lane>>3
    const int lm = lane >> 3;
    const uint32_t aOff = (uint32_t)((((lm & 1) * 8 + (lane & 7)) * ASTR +
                                      (lm >> 1) * 8) * 2);
    const uint32_t aB0 = (uint32_t)__cvta_generic_to_shared(&Asb[0][0]);
    const uint32_t aB1 = (uint32_t)__cvta_generic_to_shared(&Asb[1][0]);
    const __half2 H05 = __float2half2_rn(0.5f);
    const int myrowBase = g + (oddl ? 8 : 0);

    __syncthreads();

#pragma unroll 1
    for (int t = 0; t < TTOT; t++) {
        const uint32_t curB = (t & 1) ? aB1 : aB0;
        const uint32_t nxtB = (t & 1) ? aB0 : aB1;
        __half* An = Asb[(t & 1) ^ 1];

        // ================= Layer 1 (recurrent) =================
        if (alive) {
#pragma unroll
            for (int mt = 0; mt < 2; mt++) {
                uint32_t a[4][4];
#pragma unroll
                for (int kt = 0; kt < 4; kt++)
                    LDSM4(a[kt], curB + aOff + (uint32_t)((mt * 16 * ASTR + kt * 16) * 2));
                const int myrow = mt * 16 + myrowBase;
#pragma unroll
                for (int ni = 0; ni < 4; ni++) {
                    if (ntBeg + ni <= 25) {
                        float d0 = 0.f, d1 = 0.f, d2 = 0.f, d3 = 0.f;
#pragma unroll
                        for (int kt = 0; kt < 4; kt++) {
                            asm volatile(
                                "mma.sync.aligned.m16n8k16.row.col.f32.f16.f16.f32 "
                                "{%0,%1,%2,%3},{%4,%5,%6,%7},{%8,%9},{%0,%1,%2,%3};\n"
                                : "+f"(d0), "+f"(d1), "+f"(d2), "+f"(d3)
                                : "r"(a[kt][0]), "r"(a[kt][1]), "r"(a[kt][2]), "r"(a[kt][3]),
                                  "r"(Br[0][ni][kt][0]), "r"(Br[0][ni][kt][1]));
                        }
                        float s0 = oddl ? d0 : d2;
                        float s1 = oddl ? d1 : d3;
                        float x0 = __shfl_xor_sync(0xffffffffu, s0, 1);
                        float x1 = __shfl_xor_sync(0xffffffffu, s1, 1);
                        float gi = oddl ? x0 : d0;     // pre-scaled 0.5*g_i
                        float gf = oddl ? x1 : d1;     // pre-scaled 0.5*g_f
                        float gz = oddl ? d2 : x0;     // unscaled
                        float go = oddl ? d3 : x1;     // pre-scaled 0.5*g_o
                        __half2 t1 = tanh2_ap(__floats2half2_rn(gi, gf));
                        __half2 sif = __hfma2(t1, H05, H05);
                        __half2 t2 = tanh2_ap(__floats2half2_rn(gz, go));
                        float i_ = __low2float(sif);
                        float f_ = __high2float(sif);
                        float z_ = __low2float(t2);
                        float o_ = fmaf(__high2float(t2), 0.5f, 0.5f);
                        float c  = fmaf(f_, creg[mt][ni], i_ * z_);
                        creg[mt][ni] = c;
                        int j = 2 * (ntBeg + ni) + (tig >> 1);
                        if (j < 51)
                            An[myrow * ASTR + j] = __float2half_rn(o_ * tanh_ap(c));
                    }
                }
            }
        }
        __syncthreads();                      // S3: h1 visible

        // ================= Layer 2 (stateless) + row partials =================
        if (alive) {
            float racc[2] = {0.0f, 0.0f};
#pragma unroll
            for (int mt = 0; mt < 2; mt++) {
                uint32_t a[4][4];
#pragma unroll
                for (int kt = 0; kt < 4; kt++)
                    LDSM4(a[kt], nxtB + aOff + (uint32_t)((mt * 16 * ASTR + kt * 16) * 2));
#pragma unroll
                for (int ni = 0; ni < 4; ni++) {
                    if (ntBeg + ni <= 25) {
                        float d0 = 0.f, d1 = 0.f, d2 = 0.f, d3 = 0.f;
#pragma unroll
                        for (int kt = 0; kt < 4; kt++) {
                            asm volatile(
                                "mma.sync.aligned.m16n8k16.row.col.f32.f16.f16.f32 "
                                "{%0,%1,%2,%3},{%4,%5,%6,%7},{%8,%9},{%0,%1,%2,%3};\n"
                                : "+f"(d0), "+f"(d1), "+f"(d2), "+f"(d3)
                                : "r"(a[kt][0]), "r"(a[kt][1]), "r"(a[kt][2]), "r"(a[kt][3]),
                                  "r"(Br[1][ni][kt][0]), "r"(Br[1][ni][kt][1]));
                        }
                        float s0 = oddl ? d0 : d2;
                        float s1 = oddl ? d1 : d3;
                        float x0 = __shfl_xor_sync(0xffffffffu, s0, 1);
                        float x1 = __shfl_xor_sync(0xffffffffu, s1, 1);
                        float gi = oddl ? x0 : d0;
                        float gf = oddl ? x1 : d1;
                        float gz = oddl ? d2 : x0;
                        float go = oddl ? d3 : x1;
                        __half2 t1 = tanh2_ap(__floats2half2_rn(gi, gf));
                        __half2 sif = __hfma2(t1, H05, H05);
                        __half2 t2 = tanh2_ap(__floats2half2_rn(gz, go));
                        float i_ = __low2float(sif);
                        float f_ = __high2float(sif);
                        float z_ = __low2float(t2);
                        float o_ = fmaf(__high2float(t2), 0.5f, 0.5f);
                        float c2 = fmaf(f_, creg[mt][ni], i_ * z_);   // c NOT updated
                        racc[mt] += o_ * tanh_ap(c2) * woj[ni];
                    }
                }
            }
            racc[0] += __shfl_xor_sync(0xffffffffu, racc[0], 2);
            racc[1] += __shfl_xor_sync(0xffffffffu, racc[1], 2);
            if ((tig >> 1) == 0) {
                int rowA = myrowBase;
                Rs2[rowA * RSTR + wrp]        = racc[0];
                Rs2[(rowA + 16) * RSTR + wrp] = racc[1];
            }
        }
        // x-stage for next step (slot 51 is multiplied by zero weight in L2,
        // so overlapping with L2's reads of An is benign)
        if (tid < BT) {
            if (t + 1 < TSEQ)
                An[tid * ASTR + 51] = __float2half_rn(xnext);
            if (t + 2 < TSEQ)
                xnext = x[(size_t)(gb0 + tid) * TSEQ + (t + 2)];
        }
        __syncthreads();                      // S4: partials + staged x visible

        // ================= emit =================
        {
            int row = tid >> 3, q = tid & 7;
            float s = Rs2[row * RSTR + q];
            s += __shfl_xor_sync(0xffffffffu, s, 1);
            s += __shfl_xor_sync(0xffffffffu, s, 2);
            s += __shfl_xor_sync(0xffffffffu, s, 4);
            if (q == 0) {
                float o = s + bo;
                out[(size_t)(gb0 + row) * TTOT + t] = o;
                if (t + 1 >= TSEQ)
                    An[row * ASTR + 51] = __float2half_rn(o);   // autoregressive feed
            }
        }
        if (t >= TSEQ - 1) __syncthreads();   // S5 only when feedback was written
    }
}

// ---------------------------------------------------------------------------
extern "C" void kernel_launch(void* const* d_in, const int* in_sizes, int n_in,
                              void* d_out, int out_size) {
    const float* x    = (const float*)d_in[0];
    const float* Wih1 = (const float*)d_in[1];
    const float* Whh1 = (const float*)d_in[2];
    const float* bih1 = (const float*)d_in[3];
    const float* bhh1 = (const float*)d_in[4];
    const float* Wih2 = (const float*)d_in[5];
    const float* Whh2 = (const float*)d_in[6];
    const float* bih2 = (const float*)d_in[7];
    const float* bhh2 = (const float*)d_in[8];
    const float* Wout = (const float*)d_in[9];
    const float* bouT = (const float*)d_in[10];
    float* out = (float*)d_out;

    prep_weights<<<64, 256>>>(Wih1, Whh1, bih1, bhh1, Wih2, Whh2, bih2, bhh2);
    lstm_main<<<NCTA, TPB>>>(x, Wout, bouT, out);
}

// round 11
// speedup vs baseline: 1.0868x; 1.0868x over previous
#include <cuda_runtime.h>
#include <cuda_fp16.h>
#include <cstdint>

// LSTMPredictor: persistent-CTA fused 2-layer LSTM, layer-pipelined.
// R8: L2(t-1) and L1(t) share one set of A-fragments and one barrier per step
// (out(t) feeds nothing for t < 2047, so L2 is off the recurrence critical
// path). Autoregressive tail (64 steps) runs a separate 3-barrier loop.
// Weights + c-state in registers; f16x2 packed gate activations (0.5 prescale
// baked into weights); double-buffered operand matrix + Rs2 in SMEM.
//
// Grid 256 CTAs x 256 thr, BT=32 rows/CTA, 2 CTAs/SM.
// fp16 mma.m16n8k16: G[32 x 256pad] = A[32 x 64] @ W.
//   K: 0..50 h, 51 x/out, 52 bias(1.0), 53..63 zero
//   N: gate rows permuted n = 4j+q, q={i,f,g,o}; i/f/o rows pre-scaled 0.5.

#define NLAY_OFF 8192
#define WF_TOTAL 16384
#define ASTR 72
#define RSTR 9
#define BT   32
#define TPB  256
#define TSEQ 2048
#define TTOT 2112
#define NCTA 256

__device__ __align__(16) uint32_t d_Wf[WF_TOTAL];

__device__ __forceinline__ float tanh_ap(float x) {
    float y; asm("tanh.approx.f32 %0, %1;" : "=f"(y) : "f"(x)); return y;
}
__device__ __forceinline__ __half2 tanh2_ap(__half2 a) {
    uint32_t r, u = *(uint32_t*)&a;
    asm("tanh.approx.f16x2 %0, %1;" : "=r"(r) : "r"(u));
    return *(__half2*)&r;
}

#define LDSM4(d, addr)                                                        \
    asm volatile("ldmatrix.sync.aligned.m8n8.x4.shared.b16 {%0,%1,%2,%3}, [%4];" \
                 : "=r"(d[0]), "=r"(d[1]), "=r"(d[2]), "=r"(d[3]) : "r"(addr))

// ---------------------------------------------------------------------------
// Fragment-ordered fp16 weights (R4-R7 verified encoding; nt padded to 32).
// u = L*8192 + ((kt*32 + nt)*32 + lane)*2 + r
// pair = W[k0][n], W[k0+1][n]; k0 = kt*16 + r*8 + 2*(lane&3); n = nt*8 + (lane>>2)
// n -> gate row: j = n>>2, q = n&3, row = q*51 + j.  sigmoid rows (q != 2)
// pre-scaled by 0.5 (sig(x) = 0.5 + 0.5*tanh(0.5x)).
__global__ void prep_weights(const float* __restrict__ Wih1, const float* __restrict__ Whh1,
                             const float* __restrict__ bih1, const float* __restrict__ bhh1,
                             const float* __restrict__ Wih2, const float* __restrict__ Whh2,
                             const float* __restrict__ bih2, const float* __restrict__ bhh2) {
    int u = blockIdx.x * blockDim.x + threadIdx.x;
    if (u >= WF_TOTAL) return;
    int L    = u / NLAY_OFF;
    int w    = u - L * NLAY_OFF;
    int r    = w & 1;
    int lane = (w >> 1) & 31;
    int t2   = w >> 6;
    int nt   = t2 & 31;
    int kt   = t2 >> 5;
    int n    = nt * 8 + (lane >> 2);
    int k0   = kt * 16 + r * 8 + 2 * (lane & 3);
    float v[2];
#pragma unroll
    for (int i = 0; i < 2; i++) {
        int k = k0 + i;
        float val = 0.0f;
        if (n < 204) {
            int j = n >> 2, q = n & 3;
            int row = q * 51 + j;
            if (k < 51)
                val = (L == 0) ? Whh1[row * 51 + k]
                               : (Wih2[row * 51 + k] + Whh2[row * 51 + k]);
            else if (k == 51)
                val = (L == 0) ? Wih1[row] : 0.0f;
            else if (k == 52)
                val = (L == 0) ? (bih1[row] + bhh1[row]) : (bih2[row] + bhh2[row]);
            if (q != 2) val *= 0.5f;          // sigmoid pre-scale
        }
        v[i] = val;
    }
    __half2 h = __floats2half2_rn(v[0], v[1]);
    d_Wf[u] = *(uint32_t*)&h;
}

// ---------------------------------------------------------------------------
__device__ __forceinline__ void act_gates(float d0, float d1, float d2, float d3,
                                          int oddl,
                                          float& i_, float& f_, float& z_, float& o_) {
    const __half2 H05 = __float2half2_rn(0.5f);
    float s0 = oddl ? d0 : d2;
    float s1 = oddl ? d1 : d3;
    float x0 = __shfl_xor_sync(0xffffffffu, s0, 1);
    float x1 = __shfl_xor_sync(0xffffffffu, s1, 1);
    float gi = oddl ? x0 : d0;     // pre-scaled 0.5*g_i
    float gf = oddl ? x1 : d1;     // pre-scaled 0.5*g_f
    float gz = oddl ? d2 : x0;     // unscaled
    float go = oddl ? d3 : x1;     // pre-scaled 0.5*g_o
    __half2 t1  = tanh2_ap(__floats2half2_rn(gi, gf));
    __half2 sif = __hfma2(t1, H05, H05);
    __half2 t2  = tanh2_ap(__floats2half2_rn(gz, go));
    i_ = __low2float(sif);
    f_ = __high2float(sif);
    z_ = __low2float(t2);
    o_ = fmaf(__high2float(t2), 0.5f, 0.5f);
}

#define MMA_CHAIN(d0, d1, d2, d3, a, bset)                                    \
    _Pragma("unroll")                                                         \
    for (int kt = 0; kt < 4; kt++) {                                          \
        asm volatile(                                                         \
            "mma.sync.aligned.m16n8k16.row.col.f32.f16.f16.f32 "              \
            "{%0,%1,%2,%3},{%4,%5,%6,%7},{%8,%9},{%0,%1,%2,%3};\n"            \
            : "+f"(d0), "+f"(d1), "+f"(d2), "+f"(d3)                          \
            : "r"(a[kt][0]), "r"(a[kt][1]), "r"(a[kt][2]), "r"(a[kt][3]),     \
              "r"(bset[kt][0]), "r"(bset[kt][1]));                            \
    }

// ---------------------------------------------------------------------------
__global__ void __launch_bounds__(TPB, 2)
lstm_main(const float* __restrict__ x,
          const float* __restrict__ Wout, const float* __restrict__ bout,
          float* __restrict__ out) {
    __shared__ __half Asb[2][BT * ASTR];
    __shared__ float  Rs2d[2][BT * RSTR];

    const int tid  = threadIdx.x;
    const int lane = tid & 31;
    const int wrp  = tid >> 5;
    const int gb0  = blockIdx.x * BT;
    const int g    = lane >> 2, tig = lane & 3;
    const int oddl = tig & 1;
    const int ntBeg = wrp * 4;
    const bool alive = (ntBeg <= 25);

    // ---- one-time init ----
    for (int i = tid; i < BT * ASTR; i += TPB) {
        __half v = __float2half_rn((i % ASTR) == 52 ? 1.0f : 0.0f);
        Asb[0][i] = v; Asb[1][i] = v;
    }
    for (int i = tid; i < BT * RSTR; i += TPB) {
        Rs2d[0][i] = 0.0f; Rs2d[1][i] = 0.0f;
    }
    if (tid < BT)
        Asb[0][tid * ASTR + 51] = __float2half_rn(x[(size_t)(gb0 + tid) * TSEQ]);
    float xnext = (tid < BT) ? x[(size_t)(gb0 + tid) * TSEQ + 1] : 0.0f;

    // B fragments -> registers
    uint32_t Br[2][4][4][2];                 // [L][ni][kt][r]
#pragma unroll
    for (int L = 0; L < 2; L++)
#pragma unroll
        for (int ni = 0; ni < 4; ni++)
#pragma unroll
            for (int kt = 0; kt < 4; kt++) {
                uint2 v = *(const uint2*)&d_Wf[L * NLAY_OFF +
                            (((kt * 32) + (ntBeg + ni)) * 32 + lane) * 2];
                Br[L][ni][kt][0] = v.x; Br[L][ni][kt][1] = v.y;
            }

    const float bo = bout[0];
    float woj[4];
#pragma unroll
    for (int ni = 0; ni < 4; ni++) {
        int j = 2 * (ntBeg + ni) + (tig >> 1);
        woj[ni] = (j < 51) ? Wout[j] : 0.0f;
    }

    float creg[2][4];
#pragma unroll
    for (int mt = 0; mt < 2; mt++)
#pragma unroll
        for (int ni = 0; ni < 4; ni++) creg[mt][ni] = 0.0f;

    // ldmatrix per-lane byte offset: matrix id lm = lane>>3
    const int lm = lane >> 3;
    const uint32_t aOff = (uint32_t)((((lm & 1) * 8 + (lane & 7)) * ASTR +
                                      (lm >> 1) * 8) * 2);
    const uint32_t aB0 = (uint32_t)__cvta_generic_to_shared(&Asb[0][0]);
    const uint32_t aB1 = (uint32_t)__cvta_generic_to_shared(&Asb[1][0]);
    const int myrowBase = g + (oddl ? 8 : 0);

    __syncthreads();

    // ================= main pipelined phase: iters 0..TSEQ-1 =================
    // iter k: A-frags of [h1(k-1), x(k), 1] feed BOTH L2(k-1) (-> out(k-1))
    // and L1(k) (-> h1(k) into nxt).  ONE barrier per iteration.
#pragma unroll 1
    for (int k = 0; k < TSEQ; k++) {
        const uint32_t curB = (k & 1) ? aB1 : aB0;
        __half* An = Asb[(k & 1) ^ 1];
        float racc[2] = {0.0f, 0.0f};

        if (alive) {
#pragma unroll
            for (int mt = 0; mt < 2; mt++) {
                uint32_t a[4][4];
#pragma unroll
                for (int kt = 0; kt < 4; kt++)
                    LDSM4(a[kt], curB + aOff + (uint32_t)((mt * 16 * ASTR + kt * 16) * 2));
                const int myrow = mt * 16 + myrowBase;
#pragma unroll
                for (int ni = 0; ni < 4; ni++) {
                    if (ntBeg + ni <= 25) {
                        // ---- L2(k-1): stateless, old creg ----
                        float e0 = 0.f, e1 = 0.f, e2 = 0.f, e3 = 0.f;
                        MMA_CHAIN(e0, e1, e2, e3, a, Br[1][ni]);
                        float i2, f2, z2, o2;
                        act_gates(e0, e1, e2, e3, oddl, i2, f2, z2, o2);
                        float c2 = fmaf(f2, creg[mt][ni], i2 * z2);
                        racc[mt] += o2 * tanh_ap(c2) * woj[ni];
                        // ---- L1(k): recurrent, updates creg ----
                        float d0 = 0.f, d1 = 0.f, d2 = 0.f, d3 = 0.f;
                        MMA_CHAIN(d0, d1, d2, d3, a, Br[0][ni]);
                        float i1, f1, z1, o1;
                        act_gates(d0, d1, d2, d3, oddl, i1, f1, z1, o1);
                        float c = fmaf(f1, creg[mt][ni], i1 * z1);
                        creg[mt][ni] = c;
                        int j = 2 * (ntBeg + ni) + (tig >> 1);
                        if (j < 51)
                            An[myrow * ASTR + j] = __float2half_rn(o1 * tanh_ap(c));
                    }
                }
            }
            racc[0] += __shfl_xor_sync(0xffffffffu, racc[0], 2);
            racc[1] += __shfl_xor_sync(0xffffffffu, racc[1], 2);
            if ((tig >> 1) == 0) {
                Rs2d[k & 1][myrowBase * RSTR + wrp]        = racc[0];
                Rs2d[k & 1][(myrowBase + 16) * RSTR + wrp] = racc[1];
            }
        }
        // stage x(k+1) into nxt; prefetch x(k+2)
        if (tid < BT) {
            if (k + 1 < TSEQ)
                An[tid * ASTR + 51] = __float2half_rn(xnext);
            if (k + 2 < TSEQ)
                xnext = x[(size_t)(gb0 + tid) * TSEQ + (k + 2)];
        }
        __syncthreads();                        // the ONE barrier

        // emit out(k-1)
        if (k >= 1) {
            int row = tid >> 3, q = tid & 7;
            float s = Rs2d[k & 1][row * RSTR + q];
            s += __shfl_xor_sync(0xffffffffu, s, 1);
            s += __shfl_xor_sync(0xffffffffu, s, 2);
            s += __shfl_xor_sync(0xffffffffu, s, 4);
            if (q == 0)
                out[(size_t)(gb0 + row) * TTOT + (k - 1)] = s + bo;
        }
    }

    // ================= autoregressive tail: t = TSEQ..TTOT-1 =================
    // out(t-1) = L2(h1(t-1)) feeds x of step t -> cannot pipeline.
#pragma unroll 1
    for (int t = TSEQ; t < TTOT; t++) {
        const uint32_t curB = (t & 1) ? aB1 : aB0;
        __half* Ac = Asb[t & 1];
        __half* An = Asb[(t & 1) ^ 1];
        float racc[2] = {0.0f, 0.0f};

        // ---- L2 on h1(t-1) -> out(t-1) ----
        if (alive) {
#pragma unroll
            for (int mt = 0; mt < 2; mt++) {
                uint32_t a[4][4];
#pragma unroll
                for (int kt = 0; kt < 4; kt++)
                    LDSM4(a[kt], curB + aOff + (uint32_t)((mt * 16 * ASTR + kt * 16) * 2));
#pragma unroll
                for (int ni = 0; ni < 4; ni++) {
                    if (ntBeg + ni <= 25) {
                        float e0 = 0.f, e1 = 0.f, e2 = 0.f, e3 = 0.f;
                        MMA_CHAIN(e0, e1, e2, e3, a, Br[1][ni]);
                        float i2, f2, z2, o2;
                        act_gates(e0, e1, e2, e3, oddl, i2, f2, z2, o2);
                        float c2 = fmaf(f2, creg[mt][ni], i2 * z2);
                        racc[mt] += o2 * tanh_ap(c2) * woj[ni];
                    }
                }
            }
            racc[0] += __shfl_xor_sync(0xffffffffu, racc[0], 2);
            racc[1] += __shfl_xor_sync(0xffffffffu, racc[1], 2);
            if ((tig >> 1) == 0) {
                Rs2d[0][myrowBase * RSTR + wrp]        = racc[0];
                Rs2d[0][(myrowBase + 16) * RSTR + wrp] = racc[1];
            }
        }
        __syncthreads();

        // emit out(t-1) and feed it back into cur's x slot
        {
            int row = tid >> 3, q = tid & 7;
            float s = Rs2d[0][row * RSTR + q];
            s += __shfl_xor_sync(0xffffffffu, s, 1);
            s += __shfl_xor_sync(0xffffffffu, s, 2);
            s += __shfl_xor_sync(0xffffffffu, s, 4);
            if (q == 0) {
                float o = s + bo;
                out[(size_t)(gb0 + row) * TTOT + (t - 1)] = o;
                Ac[row * ASTR + 51] = __float2half_rn(o);
            }
        }
        __syncthreads();

        // ---- L1 on [h1(t-1), out(t-1)] -> h1(t) ----
        if (alive) {
#pragma unroll
            for (int mt = 0; mt < 2; mt++) {
                uint32_t a[4][4];
#pragma unroll
                for (int kt = 0; kt < 4; kt++)
                    LDSM4(a[kt], curB + aOff + (uint32_t)((mt * 16 * ASTR + kt * 16) * 2));
                const int myrow = mt * 16 + myrowBase;
#pragma unroll
                for (int ni = 0; ni < 4; ni++) {
                    if (ntBeg + ni <= 25) {
                        float d0 = 0.f, d1 = 0.f, d2 = 0.f, d3 = 0.f;
                        MMA_CHAIN(d0, d1, d2, d3, a, Br[0][ni]);
                        float i1, f1, z1, o1;
                        act_gates(d0, d1, d2, d3, oddl, i1, f1, z1, o1);
                        float c = fmaf(f1, creg[mt][ni], i1 * z1);
                        creg[mt][ni] = c;
                        int j = 2 * (ntBeg + ni) + (tig >> 1);
                        if (j < 51)
                            An[myrow * ASTR + j] = __float2half_rn(o1 * tanh_ap(c));
                    }
                }
            }
        }
        __syncthreads();
    }

    // ================= final emit: out(TTOT-1) = L2(h1(TTOT-1)) =================
    {
        const uint32_t curB = (TTOT & 1) ? aB1 : aB0;
        float racc[2] = {0.0f, 0.0f};
        if (alive) {
#pragma unroll
            for (int mt = 0; mt < 2; mt++) {
                uint32_t a[4][4];
#pragma unroll
                for (int kt = 0; kt < 4; kt++)
                    LDSM4(a[kt], curB + aOff + (uint32_t)((mt * 16 * ASTR + kt * 16) * 2));
#pragma unroll
                for (int ni = 0; ni < 4; ni++) {
                    if (ntBeg + ni <= 25) {
                        float e0 = 0.f, e1 = 0.f, e2 = 0.f, e3 = 0.f;
                        MMA_CHAIN(e0, e1, e2, e3, a, Br[1][ni]);
                        float i2, f2, z2, o2;
                        act_gates(e0, e1, e2, e3, oddl, i2, f2, z2, o2);
                        float c2 = fmaf(f2, creg[mt][ni], i2 * z2);
                        racc[mt] += o2 * tanh_ap(c2) * woj[ni];
                    }
                }
            }
            racc[0] += __shfl_xor_sync(0xffffffffu, racc[0], 2);
            racc[1] += __shfl_xor_sync(0xffffffffu, racc[1], 2);
            if ((tig >> 1) == 0) {
                Rs2d[0][myrowBase * RSTR + wrp]        = racc[0];
                Rs2d[0][(myrowBase + 16) * RSTR + wrp] = racc[1];
            }
        }
        __syncthreads();
        {
            int row = tid >> 3, q = tid & 7;
            float s = Rs2d[0][row * RSTR + q];
            s += __shfl_xor_sync(0xffffffffu, s, 1);
            s += __shfl_xor_sync(0xffffffffu, s, 2);
            s += __shfl_xor_sync(0xffffffffu, s, 4);
            if (q == 0)
                out[(size_t)(gb0 + row) * TTOT + (TTOT - 1)] = s + bo;
        }
    }
}

// ---------------------------------------------------------------------------
extern "C" void kernel_launch(void* const* d_in, const int* in_sizes, int n_in,
                              void* d_out, int out_size) {
    const float* x    = (const float*)d_in[0];
    const float* Wih1 = (const float*)d_in[1];
    const float* Whh1 = (const float*)d_in[2];
    const float* bih1 = (const float*)d_in[3];
    const float* bhh1 = (const float*)d_in[4];
    const float* Wih2 = (const float*)d_in[5];
    const float* Whh2 = (const float*)d_in[6];
    const float* bih2 = (const float*)d_in[7];
    const float* bhh2 = (const float*)d_in[8];
    const float* Wout = (const float*)d_in[9];
    const float* bouT = (const float*)d_in[10];
    float* out = (float*)d_out;

    prep_weights<<<64, 256>>>(Wih1, Whh1, bih1, bhh1, Wih2, Whh2, bih2, bhh2);
    lstm_main<<<NCTA, TPB>>>(x, Wout, bouT, out);
}